// round 16
// baseline (speedup 1.0000x reference)
#include <cuda_runtime.h>
#include <cuda_fp16.h>
#include <math.h>
#include <stdint.h>

#define NROWS 16384
#define FIN   512
#define FHID  256
#define PSIZE ((size_t)NROWS * FHID)      // 4,194,304 elems per partial

// ---------------- scratch (__device__ globals; no allocation) ----------------
__device__ __half g_xh [(size_t)NROWS * FIN];     // 16 MiB  x in fp16
__device__ __half g_WTh[(size_t)FHID * FIN];      // 256 KiB Wᵀ fp16
__device__ __half g_sT [(size_t)FHID * NROWS];    // 8 MiB   supportᵀ fp16
__device__ __half g_part[4 * PSIZE];              // 32 MiB  K-split partials (fp16)
__device__ int    g_cnt[256];                     // per-m-tile arrival counters
__device__ float  g_embed_fallback[PSIZE];

// ---------------- asm helpers (arch-neutral PTX, sm_80+) ----------------
__device__ __forceinline__ uint32_t smem_u32(const void* p) {
    uint32_t a;
    asm("{ .reg .u64 t; cvta.to.shared.u64 t, %1; cvt.u32.u64 %0, t; }" : "=r"(a) : "l"(p));
    return a;
}
#define CP_ASYNC16(dst, src) \
    asm volatile("cp.async.cg.shared.global [%0], [%1], 16;" :: "r"(dst), "l"(src))
#define CP_COMMIT() asm volatile("cp.async.commit_group;" ::: "memory")
#define CP_WAIT1()  asm volatile("cp.async.wait_group 1;" ::: "memory")
#define CP_WAIT0()  asm volatile("cp.async.wait_group 0;" ::: "memory")
#define LDSM4(r, a) \
    asm volatile("ldmatrix.sync.aligned.m8n8.x4.shared.b16 {%0,%1,%2,%3}, [%4];" \
        : "=r"((r)[0]), "=r"((r)[1]), "=r"((r)[2]), "=r"((r)[3]) : "r"(a))
#define MMA16816(c, a, b) \
    asm volatile("mma.sync.aligned.m16n8k16.row.col.f32.f16.f16.f32 " \
        "{%0,%1,%2,%3}, {%4,%5,%6,%7}, {%8,%9}, {%0,%1,%2,%3};" \
        : "+f"((c)[0]), "+f"((c)[1]), "+f"((c)[2]), "+f"((c)[3]) \
        : "r"((a)[0]), "r"((a)[1]), "r"((a)[2]), "r"((a)[3]), "r"((b)[0]), "r"((b)[1]))

// ====== fused prep: x -> fp16 (MLP=4), W -> WT fp16, zero counters ======
__global__ __launch_bounds__(256)
void prep_fused(const float* __restrict__ X, __half* __restrict__ Xh,
                const float* __restrict__ W, __half* __restrict__ WTh)
{
    if (blockIdx.x < 2048) {
        const size_t base = (size_t)blockIdx.x * 4096 + threadIdx.x * 4;
        float4 v[4];
        #pragma unroll
        for (int j = 0; j < 4; j++)
            v[j] = *reinterpret_cast<const float4*>(X + base + (size_t)j * 1024);
        #pragma unroll
        for (int j = 0; j < 4; j++) {
            __half2 h0 = __float22half2_rn(make_float2(v[j].x, v[j].y));
            __half2 h1 = __float22half2_rn(make_float2(v[j].z, v[j].w));
            *reinterpret_cast<uint2*>(Xh + base + (size_t)j * 1024) =
                make_uint2(*reinterpret_cast<uint32_t*>(&h0), *reinterpret_cast<uint32_t*>(&h1));
        }
    } else if (blockIdx.x < 2176) {
        __shared__ float ts[32][33];
        const int bw = blockIdx.x - 2048;
        const int f0 = (bw & 15) * 32, h0 = (bw >> 4) * 32;
        const int tx = threadIdx.x & 31, ty = threadIdx.x >> 5;
        #pragma unroll
        for (int k = 0; k < 4; k++)
            ts[ty + 8 * k][tx] = W[(size_t)(f0 + ty + 8 * k) * FHID + h0 + tx];
        __syncthreads();
        #pragma unroll
        for (int k = 0; k < 4; k++) {
            int h = h0 + ty + 8 * k, f = f0 + tx;
            WTh[(size_t)h * FIN + f] = __float2half_rn(ts[tx][ty + 8 * k]);
        }
    } else {
        g_cnt[threadIdx.x] = 0;    // zero the 256 m-tile counters each launch
    }
}

// ====== GEMM1 (HMMA, proven): sT[h][n] = WT @ x_fp16 ======
#define G1_SBST 32768
#define G1_SA   (2 * G1_SBST)
#define G1_SAST 8192
#define G1_SMEM (G1_SA + 2 * G1_SAST)
#define NCH1 (FIN / 64)

__global__ __launch_bounds__(256, 2)
void gemm1_hmma(const __half* __restrict__ WTh,
                const __half* __restrict__ Xh, __half* __restrict__ sT)
{
    extern __shared__ char sm[];
    const uint32_t sb = smem_u32(sm);
    const int tid  = threadIdx.x;
    const int lane = tid & 31, wid = tid >> 5;
    const int wm = wid >> 2, wn = wid & 3;
    const int mblk = blockIdx.x * 64, nblk = blockIdx.y * 256;

    float acc[2][8][4];
    #pragma unroll
    for (int i = 0; i < 2; i++)
        #pragma unroll
        for (int j = 0; j < 8; j++)
            #pragma unroll
            for (int q = 0; q < 4; q++) acc[i][j][q] = 0.0f;

    auto issue = [&](int c, int s) {
        const size_t k0 = (size_t)c * 64;
        #pragma unroll
        for (int i = 0; i < 8; i++) {
            int o = tid + i * 256;
            int row = o >> 3, kc = o & 7;
            uint32_t dst = sb + (uint32_t)s * G1_SBST + (uint32_t)row * 128
                         + (uint32_t)((kc ^ (row & 7)) << 4);
            CP_ASYNC16(dst, Xh + (size_t)(nblk + row) * FIN + k0 + kc * 8);
        }
        #pragma unroll
        for (int i = 0; i < 2; i++) {
            int o = tid + i * 256;
            int row = o >> 3, kc = o & 7;
            uint32_t so = (uint32_t)row * 128 + (uint32_t)((kc ^ (row & 7)) << 4);
            CP_ASYNC16(sb + G1_SA + (uint32_t)s * G1_SAST + so,
                       WTh + (size_t)(mblk + row) * FIN + k0 + kc * 8);
        }
    };
    auto compute = [&](int s) {
        const uint32_t baseB = sb + (uint32_t)s * G1_SBST;
        const uint32_t baseA = sb + G1_SA + (uint32_t)s * G1_SAST;
        #pragma unroll
        for (int kk = 0; kk < 4; kk++) {
            uint32_t ah[2][4];
            const int arow = lane & 15;
            const int uA = kk * 2 + (lane >> 4);
            #pragma unroll
            for (int mi = 0; mi < 2; mi++) {
                int r = wm * 32 + mi * 16 + arow;
                LDSM4(ah[mi], baseA + (uint32_t)r * 128 + (uint32_t)((uA ^ (r & 7)) << 4));
            }
            #pragma unroll
            for (int g = 0; g < 4; g++) {
                const int nrow = wn * 64 + g * 16 + (lane & 7) + ((lane >> 4) << 3);
                const int uB = kk * 2 + ((lane >> 3) & 1);
                uint32_t bh[4];
                LDSM4(bh, baseB + (uint32_t)nrow * 128 + (uint32_t)((uB ^ (nrow & 7)) << 4));
                #pragma unroll
                for (int mi = 0; mi < 2; mi++)
                    #pragma unroll
                    for (int q = 0; q < 2; q++)
                        MMA16816(acc[mi][g * 2 + q], ah[mi], &bh[2 * q]);
            }
        }
    };

    issue(0, 0); CP_COMMIT();
    issue(1, 1); CP_COMMIT();
    for (int c = 0; c < NCH1; ++c) {
        if (c + 1 < NCH1) CP_WAIT1(); else CP_WAIT0();
        __syncthreads();
        compute(c & 1);
        __syncthreads();
        if (c + 2 < NCH1) { issue(c + 2, c & 1); CP_COMMIT(); }
    }

    #pragma unroll
    for (int ni = 0; ni < 8; ni++) {
        const int col = nblk + wn * 64 + ni * 8 + (lane & 3) * 2;
        #pragma unroll
        for (int mi = 0; mi < 2; mi++) {
            const int h0 = mblk + wm * 32 + mi * 16 + (lane >> 2);
            const float* c = acc[mi][ni];
            __half2 v0 = __float22half2_rn(make_float2(c[0], c[1]));
            __half2 v1 = __float22half2_rn(make_float2(c[2], c[3]));
            *reinterpret_cast<__half2*>(sT + (size_t)h0 * NROWS + col) = v0;
            *reinterpret_cast<__half2*>(sT + (size_t)(h0 + 8) * NROWS + col) = v1;
        }
    }
}

// ===== GEMM2 split-K4 + fused last-block combine (bias + log_softmax) =====
#define BM2 64
#define BK2 64
#define SBST 32768
#define SA_OFF (3 * SBST)
#define SAST 8192
#define G2_SMEM (SA_OFF + 2 * SAST)
#define NCHS  (NROWS / BK2 / 4)          // 64 chunks per K-quarter

__global__ __launch_bounds__(256, 2)
void gemm2_splitk(const float* __restrict__ adj,
                  const __half* __restrict__ Bh,
                  const float* __restrict__ bias,
                  __half* __restrict__ part,
                  float* __restrict__ embed,
                  float* __restrict__ logp)
{
    extern __shared__ char sm[];
    const uint32_t sb = smem_u32(sm);
    const int tid  = threadIdx.x;
    const int lane = tid & 31, wid = tid >> 5;
    const int wm = wid >> 2, wn = wid & 3;
    const int m    = blockIdx.x & 255;
    const int kq   = blockIdx.x >> 8;
    const int mblk = m * BM2;
    const size_t kbase = (size_t)kq * (NROWS / 4);
    __half* pout = part + (size_t)kq * PSIZE;

    float acc[2][8][4];
    #pragma unroll
    for (int i = 0; i < 2; i++)
        #pragma unroll
        for (int j = 0; j < 8; j++)
            #pragma unroll
            for (int q = 0; q < 4; q++) acc[i][j][q] = 0.0f;

    auto issueB = [&](int c, int s) {
        const size_t k0 = kbase + (size_t)c * BK2;
        #pragma unroll
        for (int i = 0; i < 8; i++) {
            int o = tid + i * 256;
            int row = o >> 3, kc = o & 7;
            uint32_t dst = sb + (uint32_t)s * SBST + (uint32_t)row * 128
                         + (uint32_t)((kc ^ (row & 7)) << 4);
            CP_ASYNC16(dst, Bh + (size_t)row * NROWS + k0 + kc * 8);
        }
    };
    const int arow_ = tid >> 2, aq = tid & 3;
    auto ldgA = [&](int c, float4 av[4]) {
        const float* p = adj + (size_t)(mblk + arow_) * NROWS + kbase + (size_t)c * BK2 + aq * 16;
        av[0] = reinterpret_cast<const float4*>(p)[0];
        av[1] = reinterpret_cast<const float4*>(p)[1];
        av[2] = reinterpret_cast<const float4*>(p)[2];
        av[3] = reinterpret_cast<const float4*>(p)[3];
    };
    auto storeA = [&](const float4 av[4], int d) {
        uint32_t w[8];
        #pragma unroll
        for (int i = 0; i < 4; i++) {
            __half2 h0 = __float22half2_rn(make_float2(av[i].x, av[i].y));
            __half2 h1 = __float22half2_rn(make_float2(av[i].z, av[i].w));
            w[2 * i]     = *reinterpret_cast<uint32_t*>(&h0);
            w[2 * i + 1] = *reinterpret_cast<uint32_t*>(&h1);
        }
        uint32_t base = sb + SA_OFF + (uint32_t)d * SAST + (uint32_t)arow_ * 128;
        uint32_t u0 = (uint32_t)((aq * 2) ^ (arow_ & 7)) << 4;
        uint32_t u1 = (uint32_t)((aq * 2 + 1) ^ (arow_ & 7)) << 4;
        asm volatile("st.shared.v4.b32 [%0], {%1,%2,%3,%4};" ::
            "r"(base + u0), "r"(w[0]), "r"(w[1]), "r"(w[2]), "r"(w[3]));
        asm volatile("st.shared.v4.b32 [%0], {%1,%2,%3,%4};" ::
            "r"(base + u1), "r"(w[4]), "r"(w[5]), "r"(w[6]), "r"(w[7]));
    };
    auto compute = [&](int bs, int ad) {
        const uint32_t baseB = sb + (uint32_t)bs * SBST;
        const uint32_t baseA = sb + SA_OFF + (uint32_t)ad * SAST;
        #pragma unroll
        for (int kk = 0; kk < 4; kk++) {
            uint32_t ah[2][4];
            const int arow = lane & 15;
            const int uA = kk * 2 + (lane >> 4);
            #pragma unroll
            for (int mi = 0; mi < 2; mi++) {
                int r = wm * 32 + mi * 16 + arow;
                LDSM4(ah[mi], baseA + (uint32_t)r * 128 + (uint32_t)((uA ^ (r & 7)) << 4));
            }
            #pragma unroll
            for (int g = 0; g < 4; g++) {
                const int nrow = wn * 64 + g * 16 + (lane & 7) + ((lane >> 4) << 3);
                const int uB = kk * 2 + ((lane >> 3) & 1);
                uint32_t bh[4];
                LDSM4(bh, baseB + (uint32_t)nrow * 128 + (uint32_t)((uB ^ (nrow & 7)) << 4));
                #pragma unroll
                for (int mi = 0; mi < 2; mi++)
                    #pragma unroll
                    for (int q = 0; q < 2; q++)
                        MMA16816(acc[mi][g * 2 + q], ah[mi], &bh[2 * q]);
            }
        }
    };

    issueB(0, 0); CP_COMMIT();
    issueB(1, 1); CP_COMMIT();
    float4 av[4];
    ldgA(0, av); storeA(av, 0);
    ldgA(1, av);

    for (int c = 0; c < NCHS; ++c) {
        if (c < NCHS - 1) CP_WAIT1(); else CP_WAIT0();
        __syncthreads();
        if (c + 1 < NCHS) storeA(av, (c + 1) & 1);
        compute(c % 3, c & 1);
        if (c + 2 < NCHS) { issueB(c + 2, (c + 2) % 3); CP_COMMIT(); }
        if (c + 2 < NCHS) ldgA(c + 2, av);
    }

    // ---- epilogue: fp16 partial stores ----
    #pragma unroll
    for (int ni = 0; ni < 8; ni++) {
        const int col = wn * 64 + ni * 8 + (lane & 3) * 2;
        #pragma unroll
        for (int mi = 0; mi < 2; mi++) {
            const int r0 = mblk + wm * 32 + mi * 16 + (lane >> 2);
            const float* c = acc[mi][ni];
            __half2 v0 = __float22half2_rn(make_float2(c[0], c[1]));
            __half2 v1 = __float22half2_rn(make_float2(c[2], c[3]));
            *reinterpret_cast<__half2*>(pout + (size_t)r0 * FHID + col) = v0;
            *reinterpret_cast<__half2*>(pout + (size_t)(r0 + 8) * FHID + col) = v1;
        }
    }

    // ---- last-block-done: 4th unit of this m-tile combines + softmaxes ----
    __threadfence();
    __syncthreads();
    __shared__ int is_last;
    if (tid == 0) is_last = (atomicAdd(&g_cnt[m], 1) == 3);
    __syncthreads();
    if (!is_last) return;
    __threadfence();   // acquire: other units' partials now visible

    // warp-per-row combine (R15-proven math, fixed kq order): 8 warps x 8 rows.
    const int w = tid >> 5;
    #pragma unroll 1
    for (int rr = 0; rr < 8; rr++) {
        const int row = mblk + w * 8 + rr;
        const int c0  = lane * 8;
        const size_t i = (size_t)row * FHID + c0;

        uint4 u0 = *reinterpret_cast<const uint4*>(part + i);
        uint4 u1 = *reinterpret_cast<const uint4*>(part + PSIZE + i);
        uint4 u2 = *reinterpret_cast<const uint4*>(part + 2 * PSIZE + i);
        uint4 u3 = *reinterpret_cast<const uint4*>(part + 3 * PSIZE + i);
        float4 bv0 = *reinterpret_cast<const float4*>(bias + c0);
        float4 bv1 = *reinterpret_cast<const float4*>(bias + c0 + 4);

        float v[8];
        {
            const uint32_t* a = reinterpret_cast<const uint32_t*>(&u0);
            const uint32_t* b = reinterpret_cast<const uint32_t*>(&u1);
            const uint32_t* cc = reinterpret_cast<const uint32_t*>(&u2);
            const uint32_t* d = reinterpret_cast<const uint32_t*>(&u3);
            const float bb[8] = {bv0.x, bv0.y, bv0.z, bv0.w, bv1.x, bv1.y, bv1.z, bv1.w};
            #pragma unroll
            for (int j = 0; j < 4; j++) {
                float2 fa = __half22float2(*reinterpret_cast<const __half2*>(&a[j]));
                float2 fb = __half22float2(*reinterpret_cast<const __half2*>(&b[j]));
                float2 fc = __half22float2(*reinterpret_cast<const __half2*>(&cc[j]));
                float2 fd = __half22float2(*reinterpret_cast<const __half2*>(&d[j]));
                v[2*j]   = ((fa.x + fb.x) + (fc.x + fd.x)) + bb[2*j];
                v[2*j+1] = ((fa.y + fb.y) + (fc.y + fd.y)) + bb[2*j+1];
            }
        }
        float mx = v[0];
        #pragma unroll
        for (int j = 1; j < 8; j++) mx = fmaxf(mx, v[j]);
        #pragma unroll
        for (int o = 16; o > 0; o >>= 1)
            mx = fmaxf(mx, __shfl_xor_sync(0xffffffffu, mx, o));
        float s = 0.0f;
        #pragma unroll
        for (int j = 0; j < 8; j++) s += __expf(v[j] - mx);
        #pragma unroll
        for (int o = 16; o > 0; o >>= 1)
            s += __shfl_xor_sync(0xffffffffu, s, o);
        const float lse = mx + __logf(s);

        *reinterpret_cast<float4*>(embed + i)     = make_float4(v[0], v[1], v[2], v[3]);
        *reinterpret_cast<float4*>(embed + i + 4) = make_float4(v[4], v[5], v[6], v[7]);
        *reinterpret_cast<float4*>(logp + i)      =
            make_float4(v[0] - lse, v[1] - lse, v[2] - lse, v[3] - lse);
        *reinterpret_cast<float4*>(logp + i + 4)  =
            make_float4(v[4] - lse, v[5] - lse, v[6] - lse, v[7] - lse);
    }
}

// ================= launch =================
extern "C" void kernel_launch(void* const* d_in, const int* in_sizes, int n_in,
                              void* d_out, int out_size)
{
    const float* x   = (const float*)d_in[0];
    const float* adj = (const float*)d_in[1];
    const float* W   = (const float*)d_in[2];
    const float* b   = (const float*)d_in[3];
    float* out = (float*)d_out;

    float* embed;
    __half *xh, *WTh, *sT, *partp;
    cudaGetSymbolAddress((void**)&xh,    g_xh);
    cudaGetSymbolAddress((void**)&WTh,   g_WTh);
    cudaGetSymbolAddress((void**)&sT,    g_sT);
    cudaGetSymbolAddress((void**)&partp, g_part);

    float* logp = out;
    if (out_size >= 2 * NROWS * FHID) embed = out + PSIZE;
    else cudaGetSymbolAddress((void**)&embed, g_embed_fallback);

    cudaFuncSetAttribute(gemm1_hmma,   cudaFuncAttributeMaxDynamicSharedMemorySize, G1_SMEM);
    cudaFuncSetAttribute(gemm2_splitk, cudaFuncAttributeMaxDynamicSharedMemorySize, G2_SMEM);

    // prep: x->fp16 (MLP=4) + W->WT fp16 + zero m-tile counters
    prep_fused<<<2048 + 128 + 1, 256>>>(x, xh, W, WTh);
    // GEMM1 (HMMA): sT = WT @ xT
    gemm1_hmma<<<dim3(FHID / 64, NROWS / 256), 256, G1_SMEM>>>(WTh, xh, sT);
    // GEMM2 split-K4 with fused last-block combine + bias + log_softmax
    gemm2_splitk<<<1024, 256, G2_SMEM>>>(adj, sT, b, partp, embed, logp);
}

// round 17
// speedup vs baseline: 1.0416x; 1.0416x over previous
#include <cuda_runtime.h>
#include <cuda_fp16.h>
#include <math.h>
#include <stdint.h>

#define NROWS 16384
#define FIN   512
#define FHID  256
#define PSIZE ((size_t)NROWS * FHID)      // 4,194,304 elems per partial

// ---------------- scratch (__device__ globals; no allocation) ----------------
__device__ __half g_xh [(size_t)NROWS * FIN];     // 16 MiB  x in fp16
__device__ __half g_WTh[(size_t)FHID * FIN];      // 256 KiB Wᵀ fp16
__device__ __half g_sT [(size_t)FHID * NROWS];    // 8 MiB   supportᵀ fp16
__device__ __half g_part[4 * PSIZE];              // 32 MiB  K-split partials (fp16)
__device__ float  g_embed_fallback[PSIZE];

// ---------------- asm helpers (arch-neutral PTX, sm_80+) ----------------
__device__ __forceinline__ uint32_t smem_u32(const void* p) {
    uint32_t a;
    asm("{ .reg .u64 t; cvta.to.shared.u64 t, %1; cvt.u32.u64 %0, t; }" : "=r"(a) : "l"(p));
    return a;
}
#define CP_ASYNC16(dst, src) \
    asm volatile("cp.async.cg.shared.global [%0], [%1], 16;" :: "r"(dst), "l"(src))
#define CP_COMMIT() asm volatile("cp.async.commit_group;" ::: "memory")
#define CP_WAIT1()  asm volatile("cp.async.wait_group 1;" ::: "memory")
#define CP_WAIT0()  asm volatile("cp.async.wait_group 0;" ::: "memory")
#define LDSM4(r, a) \
    asm volatile("ldmatrix.sync.aligned.m8n8.x4.shared.b16 {%0,%1,%2,%3}, [%4];" \
        : "=r"((r)[0]), "=r"((r)[1]), "=r"((r)[2]), "=r"((r)[3]) : "r"(a))
#define MMA16816(c, a, b) \
    asm volatile("mma.sync.aligned.m16n8k16.row.col.f32.f16.f16.f32 " \
        "{%0,%1,%2,%3}, {%4,%5,%6,%7}, {%8,%9}, {%0,%1,%2,%3};" \
        : "+f"((c)[0]), "+f"((c)[1]), "+f"((c)[2]), "+f"((c)[3]) \
        : "r"((a)[0]), "r"((a)[1]), "r"((a)[2]), "r"((a)[3]), "r"((b)[0]), "r"((b)[1]))
#define STG_CS_128(addr, v) \
    asm volatile("st.global.cs.v4.f32 [%0], {%1,%2,%3,%4};" :: \
        "l"(addr), "f"((v).x), "f"((v).y), "f"((v).z), "f"((v).w) : "memory")

// ====== fused prep (R12-proven): x -> fp16 (MLP=4), W -> WT fp16 ======
__global__ __launch_bounds__(256)
void prep_fused(const float* __restrict__ X, __half* __restrict__ Xh,
                const float* __restrict__ W, __half* __restrict__ WTh)
{
    if (blockIdx.x < 2048) {
        const size_t base = (size_t)blockIdx.x * 4096 + threadIdx.x * 4;
        float4 v[4];
        #pragma unroll
        for (int j = 0; j < 4; j++)
            v[j] = *reinterpret_cast<const float4*>(X + base + (size_t)j * 1024);
        #pragma unroll
        for (int j = 0; j < 4; j++) {
            __half2 h0 = __float22half2_rn(make_float2(v[j].x, v[j].y));
            __half2 h1 = __float22half2_rn(make_float2(v[j].z, v[j].w));
            *reinterpret_cast<uint2*>(Xh + base + (size_t)j * 1024) =
                make_uint2(*reinterpret_cast<uint32_t*>(&h0), *reinterpret_cast<uint32_t*>(&h1));
        }
    } else {
        __shared__ float ts[32][33];
        const int bw = blockIdx.x - 2048;
        const int f0 = (bw & 15) * 32, h0 = (bw >> 4) * 32;
        const int tx = threadIdx.x & 31, ty = threadIdx.x >> 5;
        #pragma unroll
        for (int k = 0; k < 4; k++)
            ts[ty + 8 * k][tx] = W[(size_t)(f0 + ty + 8 * k) * FHID + h0 + tx];
        __syncthreads();
        #pragma unroll
        for (int k = 0; k < 4; k++) {
            int h = h0 + ty + 8 * k, f = f0 + tx;
            WTh[(size_t)h * FIN + f] = __float2half_rn(ts[tx][ty + 8 * k]);
        }
    }
}

// ====== GEMM1 (HMMA, proven): sT[h][n] = WT @ x_fp16 ======
#define G1_SBST 32768
#define G1_SA   (2 * G1_SBST)
#define G1_SAST 8192
#define G1_SMEM (G1_SA + 2 * G1_SAST)
#define NCH1 (FIN / 64)

__global__ __launch_bounds__(256, 2)
void gemm1_hmma(const __half* __restrict__ WTh,
                const __half* __restrict__ Xh, __half* __restrict__ sT)
{
    extern __shared__ char sm[];
    const uint32_t sb = smem_u32(sm);
    const int tid  = threadIdx.x;
    const int lane = tid & 31, wid = tid >> 5;
    const int wm = wid >> 2, wn = wid & 3;
    const int mblk = blockIdx.x * 64, nblk = blockIdx.y * 256;

    float acc[2][8][4];
    #pragma unroll
    for (int i = 0; i < 2; i++)
        #pragma unroll
        for (int j = 0; j < 8; j++)
            #pragma unroll
            for (int q = 0; q < 4; q++) acc[i][j][q] = 0.0f;

    auto issue = [&](int c, int s) {
        const size_t k0 = (size_t)c * 64;
        #pragma unroll
        for (int i = 0; i < 8; i++) {
            int o = tid + i * 256;
            int row = o >> 3, kc = o & 7;
            uint32_t dst = sb + (uint32_t)s * G1_SBST + (uint32_t)row * 128
                         + (uint32_t)((kc ^ (row & 7)) << 4);
            CP_ASYNC16(dst, Xh + (size_t)(nblk + row) * FIN + k0 + kc * 8);
        }
        #pragma unroll
        for (int i = 0; i < 2; i++) {
            int o = tid + i * 256;
            int row = o >> 3, kc = o & 7;
            uint32_t so = (uint32_t)row * 128 + (uint32_t)((kc ^ (row & 7)) << 4);
            CP_ASYNC16(sb + G1_SA + (uint32_t)s * G1_SAST + so,
                       WTh + (size_t)(mblk + row) * FIN + k0 + kc * 8);
        }
    };
    auto compute = [&](int s) {
        const uint32_t baseB = sb + (uint32_t)s * G1_SBST;
        const uint32_t baseA = sb + G1_SA + (uint32_t)s * G1_SAST;
        #pragma unroll
        for (int kk = 0; kk < 4; kk++) {
            uint32_t ah[2][4];
            const int arow = lane & 15;
            const int uA = kk * 2 + (lane >> 4);
            #pragma unroll
            for (int mi = 0; mi < 2; mi++) {
                int r = wm * 32 + mi * 16 + arow;
                LDSM4(ah[mi], baseA + (uint32_t)r * 128 + (uint32_t)((uA ^ (r & 7)) << 4));
            }
            #pragma unroll
            for (int g = 0; g < 4; g++) {
                const int nrow = wn * 64 + g * 16 + (lane & 7) + ((lane >> 4) << 3);
                const int uB = kk * 2 + ((lane >> 3) & 1);
                uint32_t bh[4];
                LDSM4(bh, baseB + (uint32_t)nrow * 128 + (uint32_t)((uB ^ (nrow & 7)) << 4));
                #pragma unroll
                for (int mi = 0; mi < 2; mi++)
                    #pragma unroll
                    for (int q = 0; q < 2; q++)
                        MMA16816(acc[mi][g * 2 + q], ah[mi], &bh[2 * q]);
            }
        }
    };

    issue(0, 0); CP_COMMIT();
    issue(1, 1); CP_COMMIT();
    for (int c = 0; c < NCH1; ++c) {
        if (c + 1 < NCH1) CP_WAIT1(); else CP_WAIT0();
        __syncthreads();
        compute(c & 1);
        __syncthreads();
        if (c + 2 < NCH1) { issue(c + 2, c & 1); CP_COMMIT(); }
    }

    #pragma unroll
    for (int ni = 0; ni < 8; ni++) {
        const int col = nblk + wn * 64 + ni * 8 + (lane & 3) * 2;
        #pragma unroll
        for (int mi = 0; mi < 2; mi++) {
            const int h0 = mblk + wm * 32 + mi * 16 + (lane >> 2);
            const float* c = acc[mi][ni];
            __half2 v0 = __float22half2_rn(make_float2(c[0], c[1]));
            __half2 v1 = __float22half2_rn(make_float2(c[2], c[3]));
            *reinterpret_cast<__half2*>(sT + (size_t)h0 * NROWS + col) = v0;
            *reinterpret_cast<__half2*>(sT + (size_t)(h0 + 8) * NROWS + col) = v1;
        }
    }
}

// ===== GEMM2 split-K4 (R13/R14-proven): grid 1024 = 4 kq x 256 m-tiles; fp16 partials =====
#define BM2 64
#define BK2 64
#define SBST 32768
#define SA_OFF (3 * SBST)
#define SAST 8192
#define G2_SMEM (SA_OFF + 2 * SAST)
#define NCHS  (NROWS / BK2 / 4)          // 64 chunks per K-quarter

__global__ __launch_bounds__(256, 2)
void gemm2_splitk(const float* __restrict__ adj,
                  const __half* __restrict__ Bh,
                  __half* __restrict__ part)
{
    extern __shared__ char sm[];
    const uint32_t sb = smem_u32(sm);
    const int tid  = threadIdx.x;
    const int lane = tid & 31, wid = tid >> 5;
    const int wm = wid >> 2, wn = wid & 3;
    const int m    = blockIdx.x & 255;
    const int kq   = blockIdx.x >> 8;
    const int mblk = m * BM2;
    const size_t kbase = (size_t)kq * (NROWS / 4);
    __half* pout = part + (size_t)kq * PSIZE;

    float acc[2][8][4];
    #pragma unroll
    for (int i = 0; i < 2; i++)
        #pragma unroll
        for (int j = 0; j < 8; j++)
            #pragma unroll
            for (int q = 0; q < 4; q++) acc[i][j][q] = 0.0f;

    auto issueB = [&](int c, int s) {
        const size_t k0 = kbase + (size_t)c * BK2;
        #pragma unroll
        for (int i = 0; i < 8; i++) {
            int o = tid + i * 256;
            int row = o >> 3, kc = o & 7;
            uint32_t dst = sb + (uint32_t)s * SBST + (uint32_t)row * 128
                         + (uint32_t)((kc ^ (row & 7)) << 4);
            CP_ASYNC16(dst, Bh + (size_t)row * NROWS + k0 + kc * 8);
        }
    };
    const int arow_ = tid >> 2, aq = tid & 3;
    auto ldgA = [&](int c, float4 av[4]) {
        const float* p = adj + (size_t)(mblk + arow_) * NROWS + kbase + (size_t)c * BK2 + aq * 16;
        av[0] = reinterpret_cast<const float4*>(p)[0];
        av[1] = reinterpret_cast<const float4*>(p)[1];
        av[2] = reinterpret_cast<const float4*>(p)[2];
        av[3] = reinterpret_cast<const float4*>(p)[3];
    };
    auto storeA = [&](const float4 av[4], int d) {
        uint32_t w[8];
        #pragma unroll
        for (int i = 0; i < 4; i++) {
            __half2 h0 = __float22half2_rn(make_float2(av[i].x, av[i].y));
            __half2 h1 = __float22half2_rn(make_float2(av[i].z, av[i].w));
            w[2 * i]     = *reinterpret_cast<uint32_t*>(&h0);
            w[2 * i + 1] = *reinterpret_cast<uint32_t*>(&h1);
        }
        uint32_t base = sb + SA_OFF + (uint32_t)d * SAST + (uint32_t)arow_ * 128;
        uint32_t u0 = (uint32_t)((aq * 2) ^ (arow_ & 7)) << 4;
        uint32_t u1 = (uint32_t)((aq * 2 + 1) ^ (arow_ & 7)) << 4;
        asm volatile("st.shared.v4.b32 [%0], {%1,%2,%3,%4};" ::
            "r"(base + u0), "r"(w[0]), "r"(w[1]), "r"(w[2]), "r"(w[3]));
        asm volatile("st.shared.v4.b32 [%0], {%1,%2,%3,%4};" ::
            "r"(base + u1), "r"(w[4]), "r"(w[5]), "r"(w[6]), "r"(w[7]));
    };
    auto compute = [&](int bs, int ad) {
        const uint32_t baseB = sb + (uint32_t)bs * SBST;
        const uint32_t baseA = sb + SA_OFF + (uint32_t)ad * SAST;
        #pragma unroll
        for (int kk = 0; kk < 4; kk++) {
            uint32_t ah[2][4];
            const int arow = lane & 15;
            const int uA = kk * 2 + (lane >> 4);
            #pragma unroll
            for (int mi = 0; mi < 2; mi++) {
                int r = wm * 32 + mi * 16 + arow;
                LDSM4(ah[mi], baseA + (uint32_t)r * 128 + (uint32_t)((uA ^ (r & 7)) << 4));
            }
            #pragma unroll
            for (int g = 0; g < 4; g++) {
                const int nrow = wn * 64 + g * 16 + (lane & 7) + ((lane >> 4) << 3);
                const int uB = kk * 2 + ((lane >> 3) & 1);
                uint32_t bh[4];
                LDSM4(bh, baseB + (uint32_t)nrow * 128 + (uint32_t)((uB ^ (nrow & 7)) << 4));
                #pragma unroll
                for (int mi = 0; mi < 2; mi++)
                    #pragma unroll
                    for (int q = 0; q < 2; q++)
                        MMA16816(acc[mi][g * 2 + q], ah[mi], &bh[2 * q]);
            }
        }
    };

    issueB(0, 0); CP_COMMIT();
    issueB(1, 1); CP_COMMIT();
    float4 av[4];
    ldgA(0, av); storeA(av, 0);
    ldgA(1, av);

    for (int c = 0; c < NCHS; ++c) {
        if (c < NCHS - 1) CP_WAIT1(); else CP_WAIT0();
        __syncthreads();
        if (c + 1 < NCHS) storeA(av, (c + 1) & 1);
        compute(c % 3, c & 1);
        if (c + 2 < NCHS) { issueB(c + 2, (c + 2) % 3); CP_COMMIT(); }
        if (c + 2 < NCHS) ldgA(c + 2, av);
    }

    // ---- epilogue: fp16 partial stores ----
    #pragma unroll
    for (int ni = 0; ni < 8; ni++) {
        const int col = wn * 64 + ni * 8 + (lane & 3) * 2;
        #pragma unroll
        for (int mi = 0; mi < 2; mi++) {
            const int r0 = mblk + wm * 32 + mi * 16 + (lane >> 2);
            const float* c = acc[mi][ni];
            __half2 v0 = __float22half2_rn(make_float2(c[0], c[1]));
            __half2 v1 = __float22half2_rn(make_float2(c[2], c[3]));
            *reinterpret_cast<__half2*>(pout + (size_t)r0 * FHID + col) = v0;
            *reinterpret_cast<__half2*>(pout + (size_t)(r0 + 8) * FHID + col) = v1;
        }
    }
}

// ===== combine v3 (R15-proven): one warp per row, zero smem/barriers; .cs stores =====
__global__ __launch_bounds__(256)
void combine_softmax(const __half* __restrict__ part, const float* __restrict__ bias,
                     float* __restrict__ embed, float* __restrict__ logp)
{
    const int t    = threadIdx.x;
    const int lane = t & 31, w = t >> 5;
    const int row  = blockIdx.x * 8 + w;
    const int c0   = lane * 8;
    const size_t i = (size_t)row * FHID + c0;

    uint4 u0 = *reinterpret_cast<const uint4*>(part + i);
    uint4 u1 = *reinterpret_cast<const uint4*>(part + PSIZE + i);
    uint4 u2 = *reinterpret_cast<const uint4*>(part + 2 * PSIZE + i);
    uint4 u3 = *reinterpret_cast<const uint4*>(part + 3 * PSIZE + i);
    float4 bv0 = *reinterpret_cast<const float4*>(bias + c0);
    float4 bv1 = *reinterpret_cast<const float4*>(bias + c0 + 4);

    float v[8];
    {
        const uint32_t* a = reinterpret_cast<const uint32_t*>(&u0);
        const uint32_t* b = reinterpret_cast<const uint32_t*>(&u1);
        const uint32_t* c = reinterpret_cast<const uint32_t*>(&u2);
        const uint32_t* d = reinterpret_cast<const uint32_t*>(&u3);
        const float bb[8] = {bv0.x, bv0.y, bv0.z, bv0.w, bv1.x, bv1.y, bv1.z, bv1.w};
        #pragma unroll
        for (int j = 0; j < 4; j++) {
            float2 fa = __half22float2(*reinterpret_cast<const __half2*>(&a[j]));
            float2 fb = __half22float2(*reinterpret_cast<const __half2*>(&b[j]));
            float2 fc = __half22float2(*reinterpret_cast<const __half2*>(&c[j]));
            float2 fd = __half22float2(*reinterpret_cast<const __half2*>(&d[j]));
            v[2*j]   = ((fa.x + fb.x) + (fc.x + fd.x)) + bb[2*j];
            v[2*j+1] = ((fa.y + fb.y) + (fc.y + fd.y)) + bb[2*j+1];
        }
    }

    float m = v[0];
    #pragma unroll
    for (int j = 1; j < 8; j++) m = fmaxf(m, v[j]);
    #pragma unroll
    for (int o = 16; o > 0; o >>= 1)
        m = fmaxf(m, __shfl_xor_sync(0xffffffffu, m, o));

    float s = 0.0f;
    #pragma unroll
    for (int j = 0; j < 8; j++) s += __expf(v[j] - m);
    #pragma unroll
    for (int o = 16; o > 0; o >>= 1)
        s += __shfl_xor_sync(0xffffffffu, s, o);
    const float lse = m + __logf(s);

    float4 e0 = make_float4(v[0], v[1], v[2], v[3]);
    float4 e1 = make_float4(v[4], v[5], v[6], v[7]);
    float4 p0 = make_float4(v[0] - lse, v[1] - lse, v[2] - lse, v[3] - lse);
    float4 p1 = make_float4(v[4] - lse, v[5] - lse, v[6] - lse, v[7] - lse);
    STG_CS_128(embed + i,     e0);
    STG_CS_128(embed + i + 4, e1);
    STG_CS_128(logp + i,      p0);
    STG_CS_128(logp + i + 4,  p1);
}

// ================= launch =================
extern "C" void kernel_launch(void* const* d_in, const int* in_sizes, int n_in,
                              void* d_out, int out_size)
{
    const float* x   = (const float*)d_in[0];
    const float* adj = (const float*)d_in[1];
    const float* W   = (const float*)d_in[2];
    const float* b   = (const float*)d_in[3];
    float* out = (float*)d_out;

    float* embed;
    __half *xh, *WTh, *sT, *partp;
    cudaGetSymbolAddress((void**)&xh,    g_xh);
    cudaGetSymbolAddress((void**)&WTh,   g_WTh);
    cudaGetSymbolAddress((void**)&sT,    g_sT);
    cudaGetSymbolAddress((void**)&partp, g_part);

    float* logp = out;
    if (out_size >= 2 * NROWS * FHID) embed = out + PSIZE;
    else cudaGetSymbolAddress((void**)&embed, g_embed_fallback);

    cudaFuncSetAttribute(gemm1_hmma,   cudaFuncAttributeMaxDynamicSharedMemorySize, G1_SMEM);
    cudaFuncSetAttribute(gemm2_splitk, cudaFuncAttributeMaxDynamicSharedMemorySize, G2_SMEM);

    // prep: x->fp16 (MLP=4) + W->WT fp16
    prep_fused<<<2048 + 128, 256>>>(x, xh, W, WTh);
    // GEMM1 (HMMA): sT = WT @ xT
    gemm1_hmma<<<dim3(FHID / 64, NROWS / 256), 256, G1_SMEM>>>(WTh, xh, sT);
    // GEMM2 split-K4 (hardware-balanced), fp16 partials
    gemm2_splitk<<<1024, 256, G2_SMEM>>>(adj, sT, partp);
    // combine v3: warp-per-row, barrier-free, streaming stores
    combine_softmax<<<NROWS / 8, 256>>>(partp, b, embed, logp);
}